// round 16
// baseline (speedup 1.0000x reference)
#include <cuda_runtime.h>
#include <math.h>
#include <stdint.h>

// Problem constants
#define HH 64
#define WW 64
#define NN 4096            // H*W
#define CC 256
#define NHEADS 8
#define HDIM 32

// ---------------- scratch (device globals; no allocation allowed) ----------
__device__ float g_part[8 * 2 * NN];
__device__ int   g_ctr[64];
__device__ float g_ixy[2 * NN];
__device__ float g_xs[CC * NN];
__device__ float g_q[CC * NN];   // [d][N], PRE-SCALED by scale*log2e, tf32-rounded
__device__ float g_k[CC * NN];   // TRANSPOSED: [head][N][32], tf32-rounded
__device__ float g_v[CC * NN];   // [d][N], tf32-rounded
__device__ float g_ao[CC * NN];

__device__ __forceinline__ float tf32r(float x) {
    asm("cvt.rna.tf32.f32 %0, %0;" : "+f"(x));
    return x;
}
__device__ __forceinline__ float4 tf32r4(float4 v) {
    v.x = tf32r(v.x); v.y = tf32r(v.y); v.z = tf32r(v.z); v.w = tf32r(v.w);
    return v;
}
__device__ __forceinline__ float ex2f(float x) {
    float y;
    asm("ex2.approx.ftz.f32 %0, %1;" : "=f"(y) : "f"(x));
    return y;
}
__device__ __forceinline__ void mma_tf32(float c[4], const uint32_t a[4],
                                         uint32_t b0, uint32_t b1) {
    asm volatile(
        "mma.sync.aligned.m16n8k8.row.col.f32.tf32.tf32.f32 "
        "{%0,%1,%2,%3},{%4,%5,%6,%7},{%8,%9},{%0,%1,%2,%3};"
        : "+f"(c[0]), "+f"(c[1]), "+f"(c[2]), "+f"(c[3])
        : "r"(a[0]), "r"(a[1]), "r"(a[2]), "r"(a[3]), "r"(b0), "r"(b1));
}
#define CP16(dst, src) \
    asm volatile("cp.async.ca.shared.global [%0], [%1], 16;" \
                 :: "r"(dst), "l"(src))
#define CP_COMMIT() asm volatile("cp.async.commit_group;")
#define CP_WAIT1()  asm volatile("cp.async.wait_group 1;")
#define CP_WAIT0()  asm volatile("cp.async.wait_group 0;")

// scale2 = 32^-0.5 * log2(e), folded into Q at projection time
#define QSCALE2 0.2550434571f

// ---------------------------------------------------------------------------
// Kernel 1: smem-tiled depthwise conv -> relu -> offset proj, fused
// cross-group reduction + coords (last block per pixel row).
// ---------------------------------------------------------------------------
#define CONV_SMEM_FLOATS 17824

__global__ __launch_bounds__(256)
void conv_offset_fused(const float* __restrict__ x,
                       const float* __restrict__ ow,
                       const float* __restrict__ w3,
                       const float* __restrict__ w5,
                       const float* __restrict__ w7,
                       const float* __restrict__ wproj)
{
    extern __shared__ float cs[];
    float* sxt = cs;                 // [32][7][70]
    float* swc = cs + 15680;         // [32][49]
    float* swp = cs + 17248;         // [2][32]
    float* red = cs + 17312;         // [4][2][64]
    __shared__ int isLast;

    int t = threadIdx.x;
    int row = blockIdx.x;
    int cz = blockIdx.y * 32;
    float ow0 = ow[0], ow1 = ow[1], ow2 = ow[2];

    for (int idx = t; idx < 32 * 49; idx += 256) {
        int c = idx / 49, ji = idx % 49;
        int j = ji / 7, i = ji % 7;
        float v = w7[(cz + c) * 49 + ji] * ow2;
        if (j >= 1 && j <= 5 && i >= 1 && i <= 5)
            v += w5[(cz + c) * 25 + (j - 1) * 5 + (i - 1)] * ow1;
        if (j >= 2 && j <= 4 && i >= 2 && i <= 4)
            v += w3[(cz + c) * 9 + (j - 2) * 3 + (i - 2)] * ow0;
        swc[idx] = v;
    }
    if (t < 32) {
        swp[t]      = wproj[cz + t];
        swp[32 + t] = wproj[CC + cz + t];
    }

    for (int idx = t; idx < 15680; idx += 256) {
        int c = idx / 490, r2 = idx % 490;
        int j = r2 / 70, col = r2 % 70 - 3;
        int yy = row + j - 3;
        float v = 0.f;
        if (yy >= 0 && yy < HH && col >= 0 && col < WW)
            v = x[(cz + c) * NN + yy * WW + col];
        sxt[idx] = v;
    }
    __syncthreads();

    int px = t & 63, cg = t >> 6;
    float a0 = 0.f, a1 = 0.f;
#pragma unroll 1
    for (int c8 = 0; c8 < 8; c8++) {
        int c = cg * 8 + c8;
        const float* xc = sxt + c * 490;
        const float* wc = swc + c * 49;
        float feat = 0.f;
#pragma unroll
        for (int j = 0; j < 7; j++)
#pragma unroll
            for (int i = 0; i < 7; i++)
                feat += xc[j * 70 + px + i] * wc[j * 7 + i];
        feat = fmaxf(feat, 0.f);
        a0 += feat * swp[c];
        a1 += feat * swp[32 + c];
    }
    red[(cg * 2 + 0) * 64 + px] = a0;
    red[(cg * 2 + 1) * 64 + px] = a1;
    __syncthreads();

    if (t < 64) {
        float s0 = red[t]      + red[128 + t] + red[256 + t] + red[384 + t];
        float s1 = red[64 + t] + red[192 + t] + red[320 + t] + red[448 + t];
        int p = row * 64 + t;
        g_part[(blockIdx.y * 2 + 0) * NN + p] = s0;
        g_part[(blockIdx.y * 2 + 1) * NN + p] = s1;
    }
    __threadfence();
    __syncthreads();
    if (t == 0) {
        int old = atomicAdd(&g_ctr[row], 1);
        isLast = (old == 7);
    }
    __syncthreads();
    if (isLast) {
        __threadfence();
        if (t < 64) {
            int p = row * 64 + t;
            float offy = 0.f, offx = 0.f;
#pragma unroll
            for (int g = 0; g < 8; g++) {
                offy += g_part[(g * 2 + 0) * NN + p];
                offx += g_part[(g * 2 + 1) * NN + p];
            }
            float refy = ((row + 0.5f) / 63.0f) * 2.0f - 1.0f;
            float refx = ((t + 0.5f) / 63.0f) * 2.0f - 1.0f;
            float gy = fminf(fmaxf(refy + tanhf(offy) * 2.0f, -1.0f), 1.0f);
            float gx = fminf(fmaxf(refx + tanhf(offx) * 2.0f, -1.0f), 1.0f);
            g_ixy[p]      = (gx + 1.0f) * 0.5f * 63.0f;
            g_ixy[NN + p] = (gy + 1.0f) * 0.5f * 63.0f;
        }
        if (t == 0) g_ctr[row] = 0;
    }
}

// ---------------------------------------------------------------------------
// Kernel 2: bilinear grid sample — 8 channels per thread
// ---------------------------------------------------------------------------
__global__ __launch_bounds__(256)
void sample_kernel(const float* __restrict__ x)
{
    int p = blockIdx.x * 256 + threadIdx.x;
    int c0 = blockIdx.y * 8;
    float ix = g_ixy[p], iy = g_ixy[NN + p];
    float x0f = floorf(ix), y0f = floorf(iy);
    float fx = ix - x0f, fy = iy - y0f;
    int x0 = min(max((int)x0f, 0), WW - 1);
    int x1 = min(x0 + 1, WW - 1);
    int y0 = min(max((int)y0f, 0), HH - 1);
    int y1 = min(y0 + 1, HH - 1);
    int i00 = y0 * WW + x0, i01 = y0 * WW + x1;
    int i10 = y1 * WW + x0, i11 = y1 * WW + x1;
    float w00 = (1.f - fx) * (1.f - fy), w01 = fx * (1.f - fy);
    float w10 = (1.f - fx) * fy,         w11 = fx * fy;
#pragma unroll
    for (int cc = 0; cc < 8; cc++) {
        const float* xc = x + (c0 + cc) * NN;
        g_xs[(c0 + cc) * NN + p] = xc[i00] * w00 + xc[i01] * w01
                                 + xc[i10] * w10 + xc[i11] * w11;
    }
}

// ---------------------------------------------------------------------------
// Kernel 3: tf32 tensor-core GEMM (R12 structure, static smem).
// mode 3 z=0: g_q = wq@x (scaled+rounded); z=1: g_k = wk@xs TRANSPOSED
// (simple store); z=2: g_v = wv@xs. mode 2: Cext = wo@g_ao (raw).
// ---------------------------------------------------------------------------
__global__ __launch_bounds__(256)
void tcgemm(const float* __restrict__ A0, const float* __restrict__ A1,
            const float* __restrict__ A2, int mode,
            const float* __restrict__ Bext, float* __restrict__ Cext)
{
    const float* A; const float* B; float* C; bool rnd;
    int z = blockIdx.z;
    if (mode == 3) {
        A = (z == 0) ? A0 : (z == 1) ? A1 : A2;
        B = (z == 0) ? Bext : g_xs;
        C = (z == 0) ? g_q : (z == 1) ? g_k : g_v;
        rnd = true;
    } else {
        A = A0; B = g_ao; C = Cext; rnd = false;
    }

    __shared__ float As[2][64][36];
    __shared__ float Bs[2][32][72];

    int t = threadIdx.x, w = t >> 5, lane = t & 31;
    int g = lane >> 2, kq = lane & 3;
    int mg = (w >> 1) * 16, nc = (w & 1) * 32;
    int m0 = blockIdx.y * 64, n0 = blockIdx.x * 64;

    float acc[4][4];
#pragma unroll
    for (int i = 0; i < 4; i++)
#pragma unroll
        for (int j = 0; j < 4; j++) acc[i][j] = 0.f;

    int am[2], ak;  ak = (t & 7) * 4;
    am[0] = t >> 3; am[1] = (t >> 3) + 32;
    int bk[2], bn;  bn = (t & 15) * 4;
    bk[0] = t >> 4; bk[1] = (t >> 4) + 16;

    float4 ra[2], rb[2];
#pragma unroll
    for (int j = 0; j < 2; j++) {
        ra[j] = tf32r4(*(const float4*)&A[(m0 + am[j]) * 256 + ak]);
        rb[j] = tf32r4(*(const float4*)&B[bk[j] * NN + n0 + bn]);
    }

    for (int ki = 0; ki < 8; ki++) {
        int b = ki & 1;
#pragma unroll
        for (int j = 0; j < 2; j++) {
            *(float4*)&As[b][am[j]][ak] = ra[j];
            *(float4*)&Bs[b][bk[j]][bn] = rb[j];
        }
        __syncthreads();
        if (ki < 7) {
            int k0 = (ki + 1) * 32;
#pragma unroll
            for (int j = 0; j < 2; j++) {
                ra[j] = tf32r4(*(const float4*)&A[(m0 + am[j]) * 256 + k0 + ak]);
                rb[j] = tf32r4(*(const float4*)&B[(k0 + bk[j]) * NN + n0 + bn]);
            }
        }
#pragma unroll
        for (int kt = 0; kt < 4; kt++) {
            uint32_t a[4];
            a[0] = __float_as_uint(As[b][mg + g][kt * 8 + kq]);
            a[1] = __float_as_uint(As[b][mg + g + 8][kt * 8 + kq]);
            a[2] = __float_as_uint(As[b][mg + g][kt * 8 + kq + 4]);
            a[3] = __float_as_uint(As[b][mg + g + 8][kt * 8 + kq + 4]);
#pragma unroll
            for (int nt = 0; nt < 4; nt++) {
                uint32_t b0 = __float_as_uint(Bs[b][kt * 8 + kq][nc + nt * 8 + g]);
                uint32_t b1 = __float_as_uint(Bs[b][kt * 8 + kq + 4][nc + nt * 8 + g]);
                mma_tf32(acc[nt], a, b0, b1);
            }
        }
    }

    if (mode == 3 && z == 0) {
#pragma unroll
        for (int i = 0; i < 4; i++)
#pragma unroll
            for (int j = 0; j < 4; j++) acc[i][j] *= QSCALE2;
    }
    if (rnd) {
#pragma unroll
        for (int i = 0; i < 4; i++)
#pragma unroll
            for (int j = 0; j < 4; j++) acc[i][j] = tf32r(acc[i][j]);
    }

    if (mode == 3 && z == 1) {
        // transposed store: g_k[head][n][dh], head=m>>5, dh=m&31
        int m1 = m0 + mg + g, m2 = m1 + 8;
        float* b1p = C + (m1 >> 5) * (NN * 32) + (m1 & 31);
        float* b2p = C + (m2 >> 5) * (NN * 32) + (m2 & 31);
#pragma unroll
        for (int nt = 0; nt < 4; nt++) {
            int col = n0 + nc + nt * 8 + 2 * kq;
            b1p[col * 32]       = acc[nt][0];
            b1p[(col + 1) * 32] = acc[nt][1];
            b2p[col * 32]       = acc[nt][2];
            b2p[(col + 1) * 32] = acc[nt][3];
        }
    } else {
#pragma unroll
        for (int nt = 0; nt < 4; nt++) {
            int col = n0 + nc + nt * 8 + 2 * kq;
            *(float2*)&C[(m0 + mg + g) * NN + col]     = make_float2(acc[nt][0], acc[nt][1]);
            *(float2*)&C[(m0 + mg + g + 8) * NN + col] = make_float2(acc[nt][2], acc[nt][3]);
        }
    }
}

// ---------------------------------------------------------------------------
// Kernel 4: flash attention v12 (best measured): factorized decay bias,
// K [key][40] one-LDS.64 frags, V [d][72] conflict-free, P in registers,
// Q pre-scaled. Om stride 33 (conflict-free writeout readback).
// ---------------------------------------------------------------------------
#define KST 40
#define VST 72
#define KS_STAGE (64 * KST)          // 2560
#define VS_STAGE (32 * VST)          // 2304
#define KS_OFF  0
#define VS_OFF  (3 * KS_STAGE)              // 7680
#define EXS_OFF (VS_OFF + 3 * VS_STAGE)     // 14592
#define EYL_OFF (EXS_OFF + 8192)            // 22784
#define LSM_OFF (EYL_OFF + 64)              // 22848
#define FLASH_SMEM_FLOATS (LSM_OFF + 128)   // 22976
#define OMS 33   // Om stride: (33*r+d)%32 = (r+d)%32 -> conflict-free readout

__global__ __launch_bounds__(256, 2)
void flash_tc12(const float* __restrict__ beta_p)
{
    extern __shared__ float sm[];
    float4* ExS4 = (float4*)(sm + EXS_OFF);
    float* EyL = sm + EYL_OFF;
    float* Lsm = sm + LSM_OFF;

    int t = threadIdx.x, w = t >> 5, lane = t & 31;
    int g = lane >> 2, kq = lane & 3;
    int mg = (w & 3) * 32;
    int ch = w >> 2;
    int cb = ch * 32;
    int n0 = blockIdx.x * 128;
    int h  = blockIdx.y;

    const float LOG2E = 1.4426950408889634f;
    float invb = 1.0f / (fabsf(beta_p[0]) + 1e-6f);
    float cdec = invb * LOG2E;

    if (t < 64) EyL[t] = ex2f(-(float)t * cdec);

#pragma unroll
    for (int rt = 0; rt < 2; rt++) {
#pragma unroll
        for (int nt = 0; nt < 4; nt++) {
            int cc  = cb + nt * 8 + 2 * kq;
            int qxA = (mg + rt * 16 + g) & 63;
            int qxB = (mg + rt * 16 + 8 + g) & 63;
            float4 ex;
            ex.x = ex2f(-(float)abs(qxA - cc)       * cdec) * LOG2E;
            ex.y = ex2f(-(float)abs(qxA - cc - 1)   * cdec) * LOG2E;
            ex.z = ex2f(-(float)abs(qxB - cc)       * cdec) * LOG2E;
            ex.w = ex2f(-(float)abs(qxB - cc - 1)   * cdec) * LOG2E;
            ExS4[(rt * 4 + nt) * 256 + t] = ex;
        }
    }

    const float* gq  = g_q + h * HDIM * NN;   // pre-scaled by QSCALE2
    const float* gkT = g_k + h * (NN * 32);   // [N][32]
    const float* gv  = g_v + h * HDIM * NN;

    int qyw = (n0 + mg) >> 6;   // warp-uniform row y

    // Q fragments with d-permutation (A-slot kq <-> d=kt*8+2kq, kq+4 <-> +1)
    uint32_t qa[2][4][4];
#pragma unroll
    for (int rt = 0; rt < 2; rt++) {
        int base = n0 + mg + rt * 16 + g;
#pragma unroll
        for (int kt = 0; kt < 4; kt++) {
            int dlo = kt * 8 + 2 * kq;
            qa[rt][kt][0] = __float_as_uint(gq[dlo * NN + base]);
            qa[rt][kt][1] = __float_as_uint(gq[dlo * NN + base + 8]);
            qa[rt][kt][2] = __float_as_uint(gq[(dlo + 1) * NN + base]);
            qa[rt][kt][3] = __float_as_uint(gq[(dlo + 1) * NN + base + 8]);
        }
    }

    float o[2][4][4];
#pragma unroll
    for (int rt = 0; rt < 2; rt++)
#pragma unroll
        for (int i = 0; i < 4; i++)
#pragma unroll
            for (int j = 0; j < 4; j++) o[rt][i][j] = 0.f;
    float l[2][2] = {{0.f, 0.f}, {0.f, 0.f}};

    int kr0 = t >> 3,  kc0 = (t & 7) * 4;
    int kr1 = kr0 + 32;
    int vr0 = t >> 4,  vc0 = (t & 15) * 4;
    int vr1 = vr0 + 16;

#define PREFETCH(stage, kcol)                                                  \
    do {                                                                       \
        float* kbase = sm + KS_OFF + (stage) * KS_STAGE;                       \
        float* vbase = sm + VS_OFF + (stage) * VS_STAGE;                       \
        unsigned dk0 = (unsigned)__cvta_generic_to_shared(&kbase[kr0 * KST + kc0]); \
        unsigned dk1 = (unsigned)__cvta_generic_to_shared(&kbase[kr1 * KST + kc0]); \
        unsigned dv0 = (unsigned)__cvta_generic_to_shared(&vbase[vr0 * VST + vc0]); \
        unsigned dv1 = (unsigned)__cvta_generic_to_shared(&vbase[vr1 * VST + vc0]); \
        CP16(dk0, &gkT[((kcol) + kr0) * 32 + kc0]);                            \
        CP16(dk1, &gkT[((kcol) + kr1) * 32 + kc0]);                            \
        CP16(dv0, &gv[vr0 * NN + (kcol) + vc0]);                               \
        CP16(dv1, &gv[vr1 * NN + (kcol) + vc0]);                               \
    } while (0)

    PREFETCH(0, 0);   CP_COMMIT();
    PREFETCH(1, 64);  CP_COMMIT();

    for (int kb = 0; kb < 64; kb++) {
        int st = kb - (kb / 3) * 3;
        if (kb < 63) CP_WAIT1(); else CP_WAIT0();
        __syncthreads();
        if (kb < 62) {
            int st2 = kb + 2; st2 -= (st2 / 3) * 3;
            PREFETCH(st2, (kb + 2) * 64);
            CP_COMMIT();
        }

        const float* Ksb = sm + KS_OFF + st * KS_STAGE;
        const float* Vsb = sm + VS_OFF + st * VS_STAGE;

        // ---- S = Q K^T ----
        float s[2][4][4];
#pragma unroll
        for (int rt = 0; rt < 2; rt++)
#pragma unroll
            for (int i = 0; i < 4; i++)
#pragma unroll
                for (int j = 0; j < 4; j++) s[rt][i][j] = 0.f;
#pragma unroll
        for (int kt = 0; kt < 4; kt++) {
#pragma unroll
            for (int nt = 0; nt < 4; nt++) {
                float2 kk = *(const float2*)&Ksb[(cb + nt * 8 + g) * KST + kt * 8 + 2 * kq];
                uint32_t b0 = __float_as_uint(kk.x);
                uint32_t b1 = __float_as_uint(kk.y);
                mma_tf32(s[0][nt], qa[0][kt], b0, b1);
                mma_tf32(s[1][nt], qa[1][kt], b0, b1);
            }
        }

        // ---- p = 2^(s + Ey*ExL) ; Ey warp-uniform per kb ----
        float ey = EyL[abs(qyw - kb)];
#pragma unroll
        for (int rt = 0; rt < 2; rt++) {
#pragma unroll
            for (int nt = 0; nt < 4; nt++) {
                float4 ex = ExS4[(rt * 4 + nt) * 256 + t];
                float p0 = ex2f(fmaf(ey, ex.x, s[rt][nt][0]));
                float p1 = ex2f(fmaf(ey, ex.y, s[rt][nt][1]));
                float p2 = ex2f(fmaf(ey, ex.z, s[rt][nt][2]));
                float p3 = ex2f(fmaf(ey, ex.w, s[rt][nt][3]));
                l[rt][0] += p0 + p1;
                l[rt][1] += p2 + p3;
                s[rt][nt][0] = tf32r(p0);
                s[rt][nt][1] = tf32r(p1);
                s[rt][nt][2] = tf32r(p2);
                s[rt][nt][3] = tf32r(p3);
            }
        }

        // ---- O += P V (pi-permuted A-frag; V rows (2kq,2kq+1) via float2) ----
#pragma unroll
        for (int kt2 = 0; kt2 < 4; kt2++) {
            uint32_t a0[4], a1[4];
            a0[0] = __float_as_uint(s[0][kt2][0]);
            a0[1] = __float_as_uint(s[0][kt2][2]);
            a0[2] = __float_as_uint(s[0][kt2][1]);
            a0[3] = __float_as_uint(s[0][kt2][3]);
            a1[0] = __float_as_uint(s[1][kt2][0]);
            a1[1] = __float_as_uint(s[1][kt2][2]);
            a1[2] = __float_as_uint(s[1][kt2][1]);
            a1[3] = __float_as_uint(s[1][kt2][3]);
#pragma unroll
            for (int nt2 = 0; nt2 < 4; nt2++) {
                float2 b01 = *(const float2*)&Vsb[(nt2 * 8 + g) * VST + cb + kt2 * 8 + 2 * kq];
                uint32_t b0 = __float_as_uint(b01.x);
                uint32_t b1 = __float_as_uint(b01.y);
                mma_tf32(o[0][nt2], a0, b0, b1);
                mma_tf32(o[1][nt2], a1, b0, b1);
            }
        }
    }

    // ---- reduce l over the 4 kq lanes ----
#pragma unroll
    for (int rt = 0; rt < 2; rt++)
#pragma unroll
        for (int hf = 0; hf < 2; hf++) {
            l[rt][hf] += __shfl_xor_sync(0xffffffffu, l[rt][hf], 1);
            l[rt][hf] += __shfl_xor_sync(0xffffffffu, l[rt][hf], 2);
        }

    // ---- merge split-K halves: O = (O_a + O_b) / (l_a + l_b) ----
    float* Om = sm;   // reuse K region [128][OMS] (4224 <= 7680 floats)
    __syncthreads();
    if (ch == 1) {
#pragma unroll
        for (int rt = 0; rt < 2; rt++) {
            int rb_ = mg + rt * 16;
            Lsm[rb_ + g] = l[rt][0];  Lsm[rb_ + g + 8] = l[rt][1];
#pragma unroll
            for (int nt = 0; nt < 4; nt++) {
                int d0 = nt * 8 + 2 * kq;
                Om[(rb_ + g) * OMS + d0]         = o[rt][nt][0];
                Om[(rb_ + g) * OMS + d0 + 1]     = o[rt][nt][1];
                Om[(rb_ + g + 8) * OMS + d0]     = o[rt][nt][2];
                Om[(rb_ + g + 8) * OMS + d0 + 1] = o[rt][nt][3];
            }
        }
    }
    __syncthreads();
    if (ch == 0) {
#pragma unroll
        for (int rt = 0; rt < 2; rt++) {
            int rb_ = mg + rt * 16;
            float iL0 = 1.0f / (l[rt][0] + Lsm[rb_ + g]);
            float iL1 = 1.0f / (l[rt][1] + Lsm[rb_ + g + 8]);
#pragma unroll
            for (int nt = 0; nt < 4; nt++) {
                int d0 = nt * 8 + 2 * kq;
                Om[(rb_ + g) * OMS + d0]         = (o[rt][nt][0] + Om[(rb_ + g) * OMS + d0])     * iL0;
                Om[(rb_ + g) * OMS + d0 + 1]     = (o[rt][nt][1] + Om[(rb_ + g) * OMS + d0 + 1]) * iL0;
                Om[(rb_ + g + 8) * OMS + d0]     = (o[rt][nt][2] + Om[(rb_ + g + 8) * OMS + d0])     * iL1;
                Om[(rb_ + g + 8) * OMS + d0 + 1] = (o[rt][nt][3] + Om[(rb_ + g + 8) * OMS + d0 + 1]) * iL1;
            }
        }
    }
    __syncthreads();

    float* go = g_ao + h * HDIM * NN;
    for (int idx = t; idx < 4096; idx += 256) {
        int r = idx & 127, d = idx >> 7;
        go[d * NN + n0 + r] = Om[r * OMS + d];
    }
}

// ---------------------------------------------------------------------------
extern "C" void kernel_launch(void* const* d_in, const int* in_sizes, int n_in,
                              void* d_out, int out_size)
{
    const float* x   = (const float*)d_in[0];
    const float* ow  = (const float*)d_in[1];
    const float* w3  = (const float*)d_in[2];
    const float* w5  = (const float*)d_in[3];
    const float* w7  = (const float*)d_in[4];
    const float* wop = (const float*)d_in[5];
    const float* wq  = (const float*)d_in[6];
    const float* wk  = (const float*)d_in[7];
    const float* wv  = (const float*)d_in[8];
    const float* wo  = (const float*)d_in[9];
    const float* beta = (const float*)d_in[10];
    float* out = (float*)d_out;

    static int smem_set = 0;
    if (!smem_set) {
        cudaFuncSetAttribute(flash_tc12, cudaFuncAttributeMaxDynamicSharedMemorySize,
                             FLASH_SMEM_FLOATS * 4);
        cudaFuncSetAttribute(conv_offset_fused, cudaFuncAttributeMaxDynamicSharedMemorySize,
                             CONV_SMEM_FLOATS * 4);
        smem_set = 1;
    }

    conv_offset_fused<<<dim3(64, 8), 256, CONV_SMEM_FLOATS * 4>>>(x, ow, w3, w5, w7, wop);
    sample_kernel<<<dim3(16, 32), 256>>>(x);
    tcgemm<<<dim3(64, 4, 3), 256>>>(wq, wk, wv, 3, x, nullptr);
    flash_tc12<<<dim3(32, 8), 256, FLASH_SMEM_FLOATS * 4>>>(beta);
    tcgemm<<<dim3(64, 4, 1), 256>>>(wo, nullptr, nullptr, 2, nullptr, out);
}

// round 17
// speedup vs baseline: 1.0361x; 1.0361x over previous
#include <cuda_runtime.h>
#include <math.h>
#include <stdint.h>

// Problem constants
#define HH 64
#define WW 64
#define NN 4096            // H*W
#define CC 256
#define NHEADS 8
#define HDIM 32

// ---------------- scratch (device globals; no allocation allowed) ----------
__device__ float g_part[8 * 2 * NN];
__device__ int   g_ctr[16];
__device__ float g_ixy[2 * NN];
__device__ float g_xs[CC * NN];
__device__ float g_q[CC * NN];   // [d][N], PRE-SCALED by scale*log2e, tf32-rounded
__device__ float g_k[CC * NN];   // TRANSPOSED: [head][N][32], tf32-rounded
__device__ float g_v[CC * NN];   // [d][N], tf32-rounded
__device__ float g_ao[CC * NN];

__device__ __forceinline__ float tf32r(float x) {
    asm("cvt.rna.tf32.f32 %0, %0;" : "+f"(x));
    return x;
}
__device__ __forceinline__ float4 tf32r4(float4 v) {
    v.x = tf32r(v.x); v.y = tf32r(v.y); v.z = tf32r(v.z); v.w = tf32r(v.w);
    return v;
}
__device__ __forceinline__ float ex2f(float x) {
    float y;
    asm("ex2.approx.ftz.f32 %0, %1;" : "=f"(y) : "f"(x));
    return y;
}
__device__ __forceinline__ void mma_tf32(float c[4], const uint32_t a[4],
                                         uint32_t b0, uint32_t b1) {
    asm volatile(
        "mma.sync.aligned.m16n8k8.row.col.f32.tf32.tf32.f32 "
        "{%0,%1,%2,%3},{%4,%5,%6,%7},{%8,%9},{%0,%1,%2,%3};"
        : "+f"(c[0]), "+f"(c[1]), "+f"(c[2]), "+f"(c[3])
        : "r"(a[0]), "r"(a[1]), "r"(a[2]), "r"(a[3]), "r"(b0), "r"(b1));
}
#define CP16(dst, src) \
    asm volatile("cp.async.ca.shared.global [%0], [%1], 16;" \
                 :: "r"(dst), "l"(src))
#define CP_COMMIT() asm volatile("cp.async.commit_group;")
#define CP_WAIT1()  asm volatile("cp.async.wait_group 1;")
#define CP_WAIT0()  asm volatile("cp.async.wait_group 0;")

// scale2 = 32^-0.5 * log2(e), folded into Q at projection time
#define QSCALE2 0.2550434571f

// ---------------------------------------------------------------------------
// Kernel 1: multi-row smem-tiled depthwise conv -> relu -> offset proj,
// fused cross-group reduction + coords (last block per 4-row group).
// grid (16 row-groups, 8 ch-groups) x 256. Block: rows bx*4..+4, ch cz..+32.
// smem: sxt[32][10][70] @0 (22400), swc[32*49] @22400 (1568), swp @23968 (64)
// ---------------------------------------------------------------------------
#define CONV_SMEM_FLOATS 24032

__global__ __launch_bounds__(256)
void conv_offset_fused(const float* __restrict__ x,
                       const float* __restrict__ ow,
                       const float* __restrict__ w3,
                       const float* __restrict__ w5,
                       const float* __restrict__ w7,
                       const float* __restrict__ wproj)
{
    extern __shared__ float cs[];
    float* sxt = cs;                 // [32][10][70]
    float* swc = cs + 22400;         // [32][49]
    float* swp = cs + 23968;         // [2][32]
    __shared__ int isLast;

    int t = threadIdx.x;
    int r0 = blockIdx.x * 4;         // first pixel row of this block
    int cz = blockIdx.y * 32;
    float ow0 = ow[0], ow1 = ow[1], ow2 = ow[2];

    // combined depthwise weights
    for (int idx = t; idx < 32 * 49; idx += 256) {
        int c = idx / 49, ji = idx % 49;
        int j = ji / 7, i = ji % 7;
        float v = w7[(cz + c) * 49 + ji] * ow2;
        if (j >= 1 && j <= 5 && i >= 1 && i <= 5)
            v += w5[(cz + c) * 25 + (j - 1) * 5 + (i - 1)] * ow1;
        if (j >= 2 && j <= 4 && i >= 2 && i <= 4)
            v += w3[(cz + c) * 9 + (j - 2) * 3 + (i - 2)] * ow0;
        swc[idx] = v;
    }
    if (t < 32) {
        swp[t]      = wproj[cz + t];
        swp[32 + t] = wproj[CC + cz + t];
    }

    // x tile: rows r0-3 .. r0+6 (10 rows), cols -3..66 (zero padded)
    for (int idx = t; idx < 22400; idx += 256) {
        int c = idx / 700, r2 = idx % 700;
        int j = r2 / 70, col = r2 % 70 - 3;
        int yy = r0 + j - 3;
        float v = 0.f;
        if (yy >= 0 && yy < HH && col >= 0 && col < WW)
            v = x[(cz + c) * NN + yy * WW + col];
        sxt[idx] = v;
    }
    __syncthreads();

    // each thread: one pixel (4 rows x 64 cols), ALL 32 channels
    int pyl = t >> 6, px = t & 63;   // local row 0..3, col 0..63
    float a0 = 0.f, a1 = 0.f;
#pragma unroll 1
    for (int c = 0; c < 32; c++) {
        const float* xc = sxt + c * 700 + pyl * 70;
        const float* wc = swc + c * 49;
        float feat = 0.f;
#pragma unroll
        for (int j = 0; j < 7; j++)
#pragma unroll
            for (int i = 0; i < 7; i++)
                feat += xc[j * 70 + px + i] * wc[j * 7 + i];
        feat = fmaxf(feat, 0.f);
        a0 += feat * swp[c];
        a1 += feat * swp[32 + c];
    }
    int p = (r0 + pyl) * 64 + px;
    g_part[(blockIdx.y * 2 + 0) * NN + p] = a0;
    g_part[(blockIdx.y * 2 + 1) * NN + p] = a1;

    __threadfence();
    __syncthreads();
    if (t == 0) {
        int old = atomicAdd(&g_ctr[blockIdx.x], 1);
        isLast = (old == 7);
    }
    __syncthreads();
    if (isLast) {
        __threadfence();
        float offy = 0.f, offx = 0.f;
#pragma unroll
        for (int g = 0; g < 8; g++) {
            offy += g_part[(g * 2 + 0) * NN + p];
            offx += g_part[(g * 2 + 1) * NN + p];
        }
        float refy = ((r0 + pyl + 0.5f) / 63.0f) * 2.0f - 1.0f;
        float refx = ((px + 0.5f) / 63.0f) * 2.0f - 1.0f;
        float gy = fminf(fmaxf(refy + tanhf(offy) * 2.0f, -1.0f), 1.0f);
        float gx = fminf(fmaxf(refx + tanhf(offx) * 2.0f, -1.0f), 1.0f);
        g_ixy[p]      = (gx + 1.0f) * 0.5f * 63.0f;
        g_ixy[NN + p] = (gy + 1.0f) * 0.5f * 63.0f;
        if (t == 0) g_ctr[blockIdx.x] = 0;
    }
}

// ---------------------------------------------------------------------------
// Kernel 2: bilinear grid sample — 4 channels per thread (R12 config)
// ---------------------------------------------------------------------------
__global__ __launch_bounds__(256)
void sample_kernel(const float* __restrict__ x)
{
    int p = blockIdx.x * 256 + threadIdx.x;
    int c0 = blockIdx.y * 4;
    float ix = g_ixy[p], iy = g_ixy[NN + p];
    float x0f = floorf(ix), y0f = floorf(iy);
    float fx = ix - x0f, fy = iy - y0f;
    int x0 = min(max((int)x0f, 0), WW - 1);
    int x1 = min(x0 + 1, WW - 1);
    int y0 = min(max((int)y0f, 0), HH - 1);
    int y1 = min(y0 + 1, HH - 1);
    int i00 = y0 * WW + x0, i01 = y0 * WW + x1;
    int i10 = y1 * WW + x0, i11 = y1 * WW + x1;
    float w00 = (1.f - fx) * (1.f - fy), w01 = fx * (1.f - fy);
    float w10 = (1.f - fx) * fy,         w11 = fx * fy;
#pragma unroll
    for (int cc = 0; cc < 4; cc++) {
        const float* xc = x + (c0 + cc) * NN;
        g_xs[(c0 + cc) * NN + p] = xc[i00] * w00 + xc[i01] * w01
                                 + xc[i10] * w10 + xc[i11] * w11;
    }
}

// ---------------------------------------------------------------------------
// Kernel 3: tf32 tensor-core GEMM (exact R12).
// ---------------------------------------------------------------------------
__global__ __launch_bounds__(256)
void tcgemm(const float* __restrict__ A0, const float* __restrict__ A1,
            const float* __restrict__ A2, int mode,
            const float* __restrict__ Bext, float* __restrict__ Cext)
{
    const float* A; const float* B; float* C; bool rnd;
    int z = blockIdx.z;
    if (mode == 3) {
        A = (z == 0) ? A0 : (z == 1) ? A1 : A2;
        B = (z == 0) ? Bext : g_xs;
        C = (z == 0) ? g_q : (z == 1) ? g_k : g_v;
        rnd = true;
    } else {
        A = A0; B = g_ao; C = Cext; rnd = false;
    }

    __shared__ float As[2][64][36];
    __shared__ float Bs[2][32][72];

    int t = threadIdx.x, w = t >> 5, lane = t & 31;
    int g = lane >> 2, kq = lane & 3;
    int mg = (w >> 1) * 16, nc = (w & 1) * 32;
    int m0 = blockIdx.y * 64, n0 = blockIdx.x * 64;

    float acc[4][4];
#pragma unroll
    for (int i = 0; i < 4; i++)
#pragma unroll
        for (int j = 0; j < 4; j++) acc[i][j] = 0.f;

    int am[2], ak;  ak = (t & 7) * 4;
    am[0] = t >> 3; am[1] = (t >> 3) + 32;
    int bk[2], bn;  bn = (t & 15) * 4;
    bk[0] = t >> 4; bk[1] = (t >> 4) + 16;

    float4 ra[2], rb[2];
#pragma unroll
    for (int j = 0; j < 2; j++) {
        ra[j] = tf32r4(*(const float4*)&A[(m0 + am[j]) * 256 + ak]);
        rb[j] = tf32r4(*(const float4*)&B[bk[j] * NN + n0 + bn]);
    }

    for (int ki = 0; ki < 8; ki++) {
        int b = ki & 1;
#pragma unroll
        for (int j = 0; j < 2; j++) {
            *(float4*)&As[b][am[j]][ak] = ra[j];
            *(float4*)&Bs[b][bk[j]][bn] = rb[j];
        }
        __syncthreads();
        if (ki < 7) {
            int k0 = (ki + 1) * 32;
#pragma unroll
            for (int j = 0; j < 2; j++) {
                ra[j] = tf32r4(*(const float4*)&A[(m0 + am[j]) * 256 + k0 + ak]);
                rb[j] = tf32r4(*(const float4*)&B[(k0 + bk[j]) * NN + n0 + bn]);
            }
        }
#pragma unroll
        for (int kt = 0; kt < 4; kt++) {
            uint32_t a[4];
            a[0] = __float_as_uint(As[b][mg + g][kt * 8 + kq]);
            a[1] = __float_as_uint(As[b][mg + g + 8][kt * 8 + kq]);
            a[2] = __float_as_uint(As[b][mg + g][kt * 8 + kq + 4]);
            a[3] = __float_as_uint(As[b][mg + g + 8][kt * 8 + kq + 4]);
#pragma unroll
            for (int nt = 0; nt < 4; nt++) {
                uint32_t b0 = __float_as_uint(Bs[b][kt * 8 + kq][nc + nt * 8 + g]);
                uint32_t b1 = __float_as_uint(Bs[b][kt * 8 + kq + 4][nc + nt * 8 + g]);
                mma_tf32(acc[nt], a, b0, b1);
            }
        }
    }

    if (mode == 3 && z == 0) {
#pragma unroll
        for (int i = 0; i < 4; i++)
#pragma unroll
            for (int j = 0; j < 4; j++) acc[i][j] *= QSCALE2;
    }
    if (rnd) {
#pragma unroll
        for (int i = 0; i < 4; i++)
#pragma unroll
            for (int j = 0; j < 4; j++) acc[i][j] = tf32r(acc[i][j]);
    }

    if (mode == 3 && z == 1) {
        int m1 = m0 + mg + g, m2 = m1 + 8;
        float* b1p = C + (m1 >> 5) * (NN * 32) + (m1 & 31);
        float* b2p = C + (m2 >> 5) * (NN * 32) + (m2 & 31);
#pragma unroll
        for (int nt = 0; nt < 4; nt++) {
            int col = n0 + nc + nt * 8 + 2 * kq;
            b1p[col * 32]       = acc[nt][0];
            b1p[(col + 1) * 32] = acc[nt][1];
            b2p[col * 32]       = acc[nt][2];
            b2p[(col + 1) * 32] = acc[nt][3];
        }
    } else {
#pragma unroll
        for (int nt = 0; nt < 4; nt++) {
            int col = n0 + nc + nt * 8 + 2 * kq;
            *(float2*)&C[(m0 + mg + g) * NN + col]     = make_float2(acc[nt][0], acc[nt][1]);
            *(float2*)&C[(m0 + mg + g + 8) * NN + col] = make_float2(acc[nt][2], acc[nt][3]);
        }
    }
}

// ---------------------------------------------------------------------------
// Kernel 4: flash attention v12 (exact R12, Om stride 36).
// ---------------------------------------------------------------------------
#define KST 40
#define VST 72
#define KS_STAGE (64 * KST)          // 2560
#define VS_STAGE (32 * VST)          // 2304
#define KS_OFF  0
#define VS_OFF  (3 * KS_STAGE)              // 7680
#define EXS_OFF (VS_OFF + 3 * VS_STAGE)     // 14592
#define EYL_OFF (EXS_OFF + 8192)            // 22784
#define LSM_OFF (EYL_OFF + 64)              // 22848
#define FLASH_SMEM_FLOATS (LSM_OFF + 128)   // 22976

__global__ __launch_bounds__(256, 2)
void flash_tc12(const float* __restrict__ beta_p)
{
    extern __shared__ float sm[];
    float4* ExS4 = (float4*)(sm + EXS_OFF);
    float* EyL = sm + EYL_OFF;
    float* Lsm = sm + LSM_OFF;

    int t = threadIdx.x, w = t >> 5, lane = t & 31;
    int g = lane >> 2, kq = lane & 3;
    int mg = (w & 3) * 32;
    int ch = w >> 2;
    int cb = ch * 32;
    int n0 = blockIdx.x * 128;
    int h  = blockIdx.y;

    const float LOG2E = 1.4426950408889634f;
    float invb = 1.0f / (fabsf(beta_p[0]) + 1e-6f);
    float cdec = invb * LOG2E;

    if (t < 64) EyL[t] = ex2f(-(float)t * cdec);

#pragma unroll
    for (int rt = 0; rt < 2; rt++) {
#pragma unroll
        for (int nt = 0; nt < 4; nt++) {
            int cc  = cb + nt * 8 + 2 * kq;
            int qxA = (mg + rt * 16 + g) & 63;
            int qxB = (mg + rt * 16 + 8 + g) & 63;
            float4 ex;
            ex.x = ex2f(-(float)abs(qxA - cc)       * cdec) * LOG2E;
            ex.y = ex2f(-(float)abs(qxA - cc - 1)   * cdec) * LOG2E;
            ex.z = ex2f(-(float)abs(qxB - cc)       * cdec) * LOG2E;
            ex.w = ex2f(-(float)abs(qxB - cc - 1)   * cdec) * LOG2E;
            ExS4[(rt * 4 + nt) * 256 + t] = ex;
        }
    }

    const float* gq  = g_q + h * HDIM * NN;   // pre-scaled by QSCALE2
    const float* gkT = g_k + h * (NN * 32);   // [N][32]
    const float* gv  = g_v + h * HDIM * NN;

    int qyw = (n0 + mg) >> 6;   // warp-uniform row y

    uint32_t qa[2][4][4];
#pragma unroll
    for (int rt = 0; rt < 2; rt++) {
        int base = n0 + mg + rt * 16 + g;
#pragma unroll
        for (int kt = 0; kt < 4; kt++) {
            int dlo = kt * 8 + 2 * kq;
            qa[rt][kt][0] = __float_as_uint(gq[dlo * NN + base]);
            qa[rt][kt][1] = __float_as_uint(gq[dlo * NN + base + 8]);
            qa[rt][kt][2] = __float_as_uint(gq[(dlo + 1) * NN + base]);
            qa[rt][kt][3] = __float_as_uint(gq[(dlo + 1) * NN + base + 8]);
        }
    }

    float o[2][4][4];
#pragma unroll
    for (int rt = 0; rt < 2; rt++)
#pragma unroll
        for (int i = 0; i < 4; i++)
#pragma unroll
            for (int j = 0; j < 4; j++) o[rt][i][j] = 0.f;
    float l[2][2] = {{0.f, 0.f}, {0.f, 0.f}};

    int kr0 = t >> 3,  kc0 = (t & 7) * 4;
    int kr1 = kr0 + 32;
    int vr0 = t >> 4,  vc0 = (t & 15) * 4;
    int vr1 = vr0 + 16;

#define PREFETCH(stage, kcol)                                                  \
    do {                                                                       \
        float* kbase = sm + KS_OFF + (stage) * KS_STAGE;                       \
        float* vbase = sm + VS_OFF + (stage) * VS_STAGE;                       \
        unsigned dk0 = (unsigned)__cvta_generic_to_shared(&kbase[kr0 * KST + kc0]); \
        unsigned dk1 = (unsigned)__cvta_generic_to_shared(&kbase[kr1 * KST + kc0]); \
        unsigned dv0 = (unsigned)__cvta_generic_to_shared(&vbase[vr0 * VST + vc0]); \
        unsigned dv1 = (unsigned)__cvta_generic_to_shared(&vbase[vr1 * VST + vc0]); \
        CP16(dk0, &gkT[((kcol) + kr0) * 32 + kc0]);                            \
        CP16(dk1, &gkT[((kcol) + kr1) * 32 + kc0]);                            \
        CP16(dv0, &gv[vr0 * NN + (kcol) + vc0]);                               \
        CP16(dv1, &gv[vr1 * NN + (kcol) + vc0]);                               \
    } while (0)

    PREFETCH(0, 0);   CP_COMMIT();
    PREFETCH(1, 64);  CP_COMMIT();

    for (int kb = 0; kb < 64; kb++) {
        int st = kb - (kb / 3) * 3;
        if (kb < 63) CP_WAIT1(); else CP_WAIT0();
        __syncthreads();
        if (kb < 62) {
            int st2 = kb + 2; st2 -= (st2 / 3) * 3;
            PREFETCH(st2, (kb + 2) * 64);
            CP_COMMIT();
        }

        const float* Ksb = sm + KS_OFF + st * KS_STAGE;
        const float* Vsb = sm + VS_OFF + st * VS_STAGE;

        float s[2][4][4];
#pragma unroll
        for (int rt = 0; rt < 2; rt++)
#pragma unroll
            for (int i = 0; i < 4; i++)
#pragma unroll
                for (int j = 0; j < 4; j++) s[rt][i][j] = 0.f;
#pragma unroll
        for (int kt = 0; kt < 4; kt++) {
#pragma unroll
            for (int nt = 0; nt < 4; nt++) {
                float2 kk = *(const float2*)&Ksb[(cb + nt * 8 + g) * KST + kt * 8 + 2 * kq];
                uint32_t b0 = __float_as_uint(kk.x);
                uint32_t b1 = __float_as_uint(kk.y);
                mma_tf32(s[0][nt], qa[0][kt], b0, b1);
                mma_tf32(s[1][nt], qa[1][kt], b0, b1);
            }
        }

        float ey = EyL[abs(qyw - kb)];
#pragma unroll
        for (int rt = 0; rt < 2; rt++) {
#pragma unroll
            for (int nt = 0; nt < 4; nt++) {
                float4 ex = ExS4[(rt * 4 + nt) * 256 + t];
                float p0 = ex2f(fmaf(ey, ex.x, s[rt][nt][0]));
                float p1 = ex2f(fmaf(ey, ex.y, s[rt][nt][1]));
                float p2 = ex2f(fmaf(ey, ex.z, s[rt][nt][2]));
                float p3 = ex2f(fmaf(ey, ex.w, s[rt][nt][3]));
                l[rt][0] += p0 + p1;
                l[rt][1] += p2 + p3;
                s[rt][nt][0] = tf32r(p0);
                s[rt][nt][1] = tf32r(p1);
                s[rt][nt][2] = tf32r(p2);
                s[rt][nt][3] = tf32r(p3);
            }
        }

#pragma unroll
        for (int kt2 = 0; kt2 < 4; kt2++) {
            uint32_t a0[4], a1[4];
            a0[0] = __float_as_uint(s[0][kt2][0]);
            a0[1] = __float_as_uint(s[0][kt2][2]);
            a0[2] = __float_as_uint(s[0][kt2][1]);
            a0[3] = __float_as_uint(s[0][kt2][3]);
            a1[0] = __float_as_uint(s[1][kt2][0]);
            a1[1] = __float_as_uint(s[1][kt2][2]);
            a1[2] = __float_as_uint(s[1][kt2][1]);
            a1[3] = __float_as_uint(s[1][kt2][3]);
#pragma unroll
            for (int nt2 = 0; nt2 < 4; nt2++) {
                float2 b01 = *(const float2*)&Vsb[(nt2 * 8 + g) * VST + cb + kt2 * 8 + 2 * kq];
                uint32_t b0 = __float_as_uint(b01.x);
                uint32_t b1 = __float_as_uint(b01.y);
                mma_tf32(o[0][nt2], a0, b0, b1);
                mma_tf32(o[1][nt2], a1, b0, b1);
            }
        }
    }

#pragma unroll
    for (int rt = 0; rt < 2; rt++)
#pragma unroll
        for (int hf = 0; hf < 2; hf++) {
            l[rt][hf] += __shfl_xor_sync(0xffffffffu, l[rt][hf], 1);
            l[rt][hf] += __shfl_xor_sync(0xffffffffu, l[rt][hf], 2);
        }

    float* Om = sm;   // reuse K region [128][36]
    __syncthreads();
    if (ch == 1) {
#pragma unroll
        for (int rt = 0; rt < 2; rt++) {
            int rb_ = mg + rt * 16;
            Lsm[rb_ + g] = l[rt][0];  Lsm[rb_ + g + 8] = l[rt][1];
#pragma unroll
            for (int nt = 0; nt < 4; nt++) {
                int d0 = nt * 8 + 2 * kq;
                Om[(rb_ + g) * 36 + d0]         = o[rt][nt][0];
                Om[(rb_ + g) * 36 + d0 + 1]     = o[rt][nt][1];
                Om[(rb_ + g + 8) * 36 + d0]     = o[rt][nt][2];
                Om[(rb_ + g + 8) * 36 + d0 + 1] = o[rt][nt][3];
            }
        }
    }
    __syncthreads();
    if (ch == 0) {
#pragma unroll
        for (int rt = 0; rt < 2; rt++) {
            int rb_ = mg + rt * 16;
            float iL0 = 1.0f / (l[rt][0] + Lsm[rb_ + g]);
            float iL1 = 1.0f / (l[rt][1] + Lsm[rb_ + g + 8]);
#pragma unroll
            for (int nt = 0; nt < 4; nt++) {
                int d0 = nt * 8 + 2 * kq;
                Om[(rb_ + g) * 36 + d0]         = (o[rt][nt][0] + Om[(rb_ + g) * 36 + d0])     * iL0;
                Om[(rb_ + g) * 36 + d0 + 1]     = (o[rt][nt][1] + Om[(rb_ + g) * 36 + d0 + 1]) * iL0;
                Om[(rb_ + g + 8) * 36 + d0]     = (o[rt][nt][2] + Om[(rb_ + g + 8) * 36 + d0])     * iL1;
                Om[(rb_ + g + 8) * 36 + d0 + 1] = (o[rt][nt][3] + Om[(rb_ + g + 8) * 36 + d0 + 1]) * iL1;
            }
        }
    }
    __syncthreads();

    float* go = g_ao + h * HDIM * NN;
    for (int idx = t; idx < 4096; idx += 256) {
        int r = idx & 127, d = idx >> 7;
        go[d * NN + n0 + r] = Om[r * 36 + d];
    }
}

// ---------------------------------------------------------------------------
extern "C" void kernel_launch(void* const* d_in, const int* in_sizes, int n_in,
                              void* d_out, int out_size)
{
    const float* x   = (const float*)d_in[0];
    const float* ow  = (const float*)d_in[1];
    const float* w3  = (const float*)d_in[2];
    const float* w5  = (const float*)d_in[3];
    const float* w7  = (const float*)d_in[4];
    const float* wop = (const float*)d_in[5];
    const float* wq  = (const float*)d_in[6];
    const float* wk  = (const float*)d_in[7];
    const float* wv  = (const float*)d_in[8];
    const float* wo  = (const float*)d_in[9];
    const float* beta = (const float*)d_in[10];
    float* out = (float*)d_out;

    static int smem_set = 0;
    if (!smem_set) {
        cudaFuncSetAttribute(flash_tc12, cudaFuncAttributeMaxDynamicSharedMemorySize,
                             FLASH_SMEM_FLOATS * 4);
        cudaFuncSetAttribute(conv_offset_fused, cudaFuncAttributeMaxDynamicSharedMemorySize,
                             CONV_SMEM_FLOATS * 4);
        smem_set = 1;
    }

    conv_offset_fused<<<dim3(16, 8), 256, CONV_SMEM_FLOATS * 4>>>(x, ow, w3, w5, w7, wop);
    sample_kernel<<<dim3(16, 64), 256>>>(x);
    tcgemm<<<dim3(64, 4, 3), 256>>>(wq, wk, wv, 3, x, nullptr);
    flash_tc12<<<dim3(32, 8), 256, FLASH_SMEM_FLOATS * 4>>>(beta);
    tcgemm<<<dim3(64, 4, 1), 256>>>(wo, nullptr, nullptr, 2, nullptr, out);
}